// round 12
// baseline (speedup 1.0000x reference)
#include <cuda_runtime.h>
#include <cstdint>
#include <math.h>

#define BATCH 8
#define LSEQ  2048
#define DIM   300
#define HH    150
#define HSP   160
#define NRTOT (BATCH*LSEQ)

typedef unsigned long long ull;

__device__ __forceinline__ float rtf(float x){
    uint32_t r; asm("cvt.rna.tf32.f32 %0, %1;" : "=r"(r) : "f"(x));
    return __uint_as_float(r);
}
__device__ __forceinline__ uint32_t rtfu(float x){
    uint32_t r; asm("cvt.rna.tf32.f32 %0, %1;" : "=r"(r) : "f"(x));
    return r;
}
__device__ __forceinline__ uint32_t smem_u32(const void* p){
    uint32_t a; asm("{ .reg .u64 t; cvta.to.shared.u64 t, %1; cvt.u32.u64 %0, t; }" : "=r"(a) : "l"(p));
    return a;
}
__device__ __forceinline__ void mma1688(float* c, const uint32_t* a, uint32_t b0, uint32_t b1){
    asm volatile(
        "mma.sync.aligned.m16n8k8.row.col.f32.tf32.tf32.f32 "
        "{%0,%1,%2,%3}, {%4,%5,%6,%7}, {%8,%9}, {%0,%1,%2,%3};"
        : "+f"(c[0]), "+f"(c[1]), "+f"(c[2]), "+f"(c[3])
        : "r"(a[0]), "r"(a[1]), "r"(a[2]), "r"(a[3]), "r"(b0), "r"(b1));
}
__device__ __forceinline__ void cp16(uint32_t smem_addr, const void* gptr){
    asm volatile("cp.async.cg.shared.global [%0], [%1], 16;" :: "r"(smem_addr), "l"(gptr));
}
__device__ __forceinline__ void cp16z(uint32_t smem_addr, const void* gptr, uint32_t srcb){
    asm volatile("cp.async.cg.shared.global [%0], [%1], 16, %2;" :: "r"(smem_addr), "l"(gptr), "r"(srcb));
}
#define CP_COMMIT() asm volatile("cp.async.commit_group;" ::: "memory")
#define CP_WAIT1()  asm volatile("cp.async.wait_group 1;"  ::: "memory")

// k-pair permutation within 8-blocks: col c -> pos ((c&3)<<1)|((c>>2)&1).
// Positions (2t, 2t+1) then hold cols (t, t+4): one LDS.64 per B fragment.
__device__ __forceinline__ int kperm(int c){
    return (c & ~7) | ((c & 3) << 1) | ((c >> 2) & 1);
}

// ---------------- scratch ----------------
__device__ __align__(16) float g_QW [NRTOT*HSP];      // h-dim k-permuted
__device__ __align__(16) float g_QhT[BATCH*HSP*LSEQ]; // q-dim k-permuted
__device__ __align__(16) float g_Ah [NRTOT*HSP];
__device__ __align__(16) float g_Hm [NRTOT*HSP];
__device__ __align__(16) float g_Wcat[320*320];
__device__ __align__(16) float g_WgT [160*160];
__device__ __align__(16) float g_WtT [160*320];

// =====================================================================
// Kernel 0: weight prep
// =====================================================================
__global__ void __launch_bounds__(256) prep_kernel(
    const float* __restrict__ Wi, const float* __restrict__ Wu,
    const float* __restrict__ Wg, const float* __restrict__ Wt)
{
    int idx = blockIdx.x*256 + threadIdx.x;
    if (idx < 320*320){
        int n = idx / 320, k = idx - n*320;
        float v = 0.f;
        if (k < 300){
            if (n < 150)                  v = Wi[k*HH + n];
            else if (n >= 160 && n < 310) v = Wu[k*HH + (n-160)];
        }
        g_Wcat[idx] = rtf(v);
    }
    if (idx < 160*160){
        int n = idx / 160, k = idx - n*160;
        float v = (n < 150 && k < 150) ? Wg[k*HH + n] : 0.f;
        g_WgT[idx] = rtf(v);
    }
    if (idx < 160*320){
        int n = idx / 320, k = idx - n*320;
        float v = 0.f;
        if (n < 150){
            if (k < 150)                  v = Wt[k*HH + n];
            else if (k >= 160 && k < 310) v = Wt[(k - 160 + 150)*HH + n];
        }
        g_WtT[idx] = rtf(v);
    }
}

// =====================================================================
// Kernel 1: gate projections (mma tf32) + fused QW GEMM for the Q path.
// Q path: g_QhT columns written at kperm(q); g_QW cols at kperm(h).
// =====================================================================
#define GT_ABUF 2304
#define GT_BBUF 11520
#define GT_SMEM ((2*GT_ABUF + 2*GT_BBUF)*4)

template<bool IS_Q>
__global__ void __launch_bounds__(256) gate_tc_kernel(
    const float* __restrict__ X,
    const float* __restrict__ bi, const float* __restrict__ bu,
    const float* __restrict__ bg)
{
    extern __shared__ __align__(16) float smem[];
    float* As = smem;
    float* Bs = smem + 2*GT_ABUF;

    const int tid = threadIdx.x, lane = tid & 31, wid = tid >> 5;
    const int wm = wid & 1, wn = wid >> 1;
    const int g = lane >> 2, t = lane & 3;
    const int row0 = blockIdx.x * 64;

    const float* __restrict__ Ap = X + (size_t)row0*DIM;
    const uint32_t sA = smem_u32(As);
    const uint32_t sB = smem_u32(Bs);

    float acc[2][10][4];
    #pragma unroll
    for (int i = 0; i < 2; i++)
        #pragma unroll
        for (int n = 0; n < 10; n++)
            #pragma unroll
            for (int k = 0; k < 4; k++) acc[i][n][k] = 0.f;

    auto stage = [&](int c, int buf){
        const int kc = c*32;
        #pragma unroll
        for (int i = 0; i < 2; i++){
            int idx = tid + i*256;
            int r = idx >> 3, kq = idx & 7;
            int gk = kc + kq*4;
            uint32_t srcb = (gk + 4 <= DIM) ? 16u : 0u;
            const float* src = srcb ? (Ap + (size_t)r*DIM + gk) : Ap;
            cp16z(sA + (uint32_t)(buf*GT_ABUF + r*36 + kq*4)*4, src, srcb);
        }
        #pragma unroll
        for (int i = 0; i < 10; i++){
            int idx = tid + i*256;
            int r = idx >> 3, kq = idx & 7;
            cp16(sB + (uint32_t)(buf*GT_BBUF + r*36 + kq*4)*4,
                 g_Wcat + r*320 + kc + kq*4);
        }
    };

    stage(0, 0); CP_COMMIT();

    #pragma unroll 1
    for (int c = 0; c < 10; c++){
        if (c + 1 < 10) stage(c+1, (c+1)&1);
        CP_COMMIT();
        CP_WAIT1();
        __syncthreads();

        const float* Ab = As + (c&1)*GT_ABUF;
        const float* Bb = Bs + (c&1)*GT_BBUF;
        #pragma unroll
        for (int k0 = 0; k0 < 32; k0 += 8){
            uint32_t afr[2][4];
            #pragma unroll
            for (int mt = 0; mt < 2; mt++){
                const int m = wm*32 + mt*16;
                afr[mt][0] = rtfu(Ab[(m+g  )*36 + k0 + t    ]);
                afr[mt][1] = rtfu(Ab[(m+g+8)*36 + k0 + t    ]);
                afr[mt][2] = rtfu(Ab[(m+g  )*36 + k0 + t + 4]);
                afr[mt][3] = rtfu(Ab[(m+g+8)*36 + k0 + t + 4]);
            }
            #pragma unroll
            for (int nt = 0; nt < 10; nt++){
                const int n = (nt < 5) ? (wn*40 + nt*8) : (160 + wn*40 + (nt-5)*8);
                uint32_t b0 = __float_as_uint(Bb[(n+g)*36 + k0 + t    ]);
                uint32_t b1 = __float_as_uint(Bb[(n+g)*36 + k0 + t + 4]);
                mma1688(acc[0][nt], afr[0], b0, b1);
                mma1688(acc[1][nt], afr[1], b0, b1);
            }
        }
        __syncthreads();
    }
    __syncthreads();

    #pragma unroll
    for (int mt = 0; mt < 2; mt++){
        #pragma unroll
        for (int j2 = 0; j2 < 2; j2++){
            const int rl = wm*32 + mt*16 + g + j2*8;
            const int r  = row0 + rl;
            const int b = r >> 11, q = r & (LSEQ-1);
            const int qp = kperm(q);
            #pragma unroll
            for (int ntp = 0; ntp < 5; ntp++){
                const int ncol = wn*40 + ntp*8 + 2*t;
                float h0 = 0.f, h1 = 0.f;
                if (ncol < HH){
                    float xi0 = acc[mt][ntp  ][2*j2    ] + __ldg(bi + ncol);
                    float xi1 = acc[mt][ntp  ][2*j2 + 1] + __ldg(bi + ncol + 1);
                    float xu0 = acc[mt][ntp+5][2*j2    ] + __ldg(bu + ncol);
                    float xu1 = acc[mt][ntp+5][2*j2 + 1] + __ldg(bu + ncol + 1);
                    h0 = rtf((1.f/(1.f + __expf(-xi0))) * tanhf(xu0));
                    h1 = rtf((1.f/(1.f + __expf(-xi1))) * tanhf(xu1));
                }
                if (IS_Q){
                    *(float2*)(Bs + rl*164 + ncol) = make_float2(h0, h1);
                    g_QhT[((size_t)b*HSP + ncol    )*LSEQ + qp] = h0;
                    g_QhT[((size_t)b*HSP + ncol + 1)*LSEQ + qp] = h1;
                } else {
                    *(float2*)(g_Ah + (size_t)r*HSP + ncol) = make_float2(h0, h1);
                }
            }
        }
    }

    if (IS_Q){
        const float* qhS = Bs;
        float* wgS = Bs + 10496;
        const uint32_t sWg = smem_u32(wgS);

        float acc2[2][5][4];
        #pragma unroll
        for (int i = 0; i < 2; i++)
            #pragma unroll
            for (int n = 0; n < 5; n++)
                #pragma unroll
                for (int k = 0; k < 4; k++) acc2[i][n][k] = 0.f;

        auto stageW = [&](int c, int buf){
            const int kc = c*32;
            #pragma unroll
            for (int i = 0; i < 5; i++){
                int idx = tid + i*256;
                int r = idx >> 3, kq = idx & 7;
                cp16(sWg + (uint32_t)(buf*5760 + r*36 + kq*4)*4,
                     g_WgT + r*160 + kc + kq*4);
            }
        };
        stageW(0, 0); CP_COMMIT();

        #pragma unroll 1
        for (int c = 0; c < 5; c++){
            if (c + 1 < 5) stageW(c+1, (c+1)&1);
            CP_COMMIT();
            CP_WAIT1();
            __syncthreads();

            const float* Wb = wgS + (c&1)*5760;
            #pragma unroll
            for (int k0 = 0; k0 < 32; k0 += 8){
                const int kk = c*32 + k0;
                uint32_t af[2][4];
                #pragma unroll
                for (int mt = 0; mt < 2; mt++){
                    const int m = wm*32 + mt*16;
                    af[mt][0] = __float_as_uint(qhS[(m+g  )*164 + kk + t    ]);
                    af[mt][1] = __float_as_uint(qhS[(m+g+8)*164 + kk + t    ]);
                    af[mt][2] = __float_as_uint(qhS[(m+g  )*164 + kk + t + 4]);
                    af[mt][3] = __float_as_uint(qhS[(m+g+8)*164 + kk + t + 4]);
                }
                #pragma unroll
                for (int nt = 0; nt < 5; nt++){
                    const int n = wn*40 + nt*8;
                    uint32_t b0 = __float_as_uint(Wb[(n+g)*36 + k0 + t    ]);
                    uint32_t b1 = __float_as_uint(Wb[(n+g)*36 + k0 + t + 4]);
                    mma1688(acc2[0][nt], af[0], b0, b1);
                    mma1688(acc2[1][nt], af[1], b0, b1);
                }
            }
            __syncthreads();
        }

        #pragma unroll
        for (int mt = 0; mt < 2; mt++){
            #pragma unroll
            for (int j2 = 0; j2 < 2; j2++){
                const int r = row0 + wm*32 + mt*16 + g + j2*8;
                #pragma unroll
                for (int nt = 0; nt < 5; nt++){
                    const int ncol = wn*40 + nt*8 + 2*t;
                    float v0 = 0.f, v1 = 0.f;
                    if (ncol < HH){
                        v0 = rtf(acc2[mt][nt][2*j2    ] + __ldg(bg + ncol));
                        v1 = rtf(acc2[mt][nt][2*j2 + 1] + __ldg(bg + ncol + 1));
                    }
                    g_QW[(size_t)r*HSP + kperm(ncol    )] = v0;
                    g_QW[(size_t)r*HSP + kperm(ncol + 1)] = v1;
                }
            }
        }
    }
}

// =====================================================================
// Kernel 2 (flash): R10 shape (128 rows, 256 thr, q-chunks 32, A hoisted,
// no-max softmax) + paired LDS.64 B loads at the ORIGINAL strides 164/36
// (both == 4 mod 32 -> bank-slot 4g+2t, exactly 2 lanes/bank: clean).
// =====================================================================
#define FL_QW_OFF  20992
#define FL_QHT_OFF (20992 + 10496)
#define FL_SMEM    ((20992 + 10496 + 11520)*4)

__global__ void __launch_bounds__(256, 1) flash_kernel()
{
    extern __shared__ __align__(16) float smem[];
    float* sAh  = smem;                  // [128][164]
    float* sQW  = smem + FL_QW_OFF;      // [2][32][164]  (h k-permuted)
    float* sQhT = smem + FL_QHT_OFF;     // [2][160][36]  (q k-permuted)

    const int tid = threadIdx.x, lane = tid & 31, w = tid >> 5;
    const int g = lane >> 2, t = lane & 3;
    const int b = blockIdx.y, a0 = blockIdx.x*128;
    const int m0 = w*16;

    const uint32_t sbAh  = smem_u32(sAh);
    const uint32_t sbQW  = smem_u32(sQW);
    const uint32_t sbQhT = smem_u32(sQhT);

    const float* __restrict__ AhP  = g_Ah  + ((size_t)b*LSEQ + a0)*HSP;
    const float* __restrict__ QWP  = g_QW  + (size_t)b*LSEQ*HSP;
    const float* __restrict__ QhTP = g_QhT + (size_t)b*HSP*LSEQ;

    #pragma unroll
    for (int i = 0; i < 20; i++){
        int idx = tid + i*256;
        int r = idx / 40, kq = idx - r*40;
        cp16(sbAh + (uint32_t)(r*164 + kq*4)*4, AhP + (size_t)r*HSP + kq*4);
    }
    auto stageQ = [&](int c, int buf){
        const int qc = c*32;
        #pragma unroll
        for (int i = 0; i < 5; i++){
            int idx = tid + i*256;
            int r = idx / 40, kq = idx - r*40;
            cp16(sbQW + (uint32_t)(buf*(32*164) + r*164 + kq*4)*4,
                 QWP + (size_t)(qc + r)*HSP + kq*4);
        }
        #pragma unroll
        for (int i = 0; i < 5; i++){
            int idx = tid + i*256;
            int r = idx >> 3, qq = idx & 7;
            cp16(sbQhT + (uint32_t)(buf*(160*36) + r*36 + qq*4)*4,
                 QhTP + (size_t)r*LSEQ + qc + qq*4);
        }
    };
    stageQ(0, 0); CP_COMMIT();
    stageQ(1, 1); CP_COMMIT();

    CP_WAIT1();
    __syncthreads();
    uint32_t afr[20][4];
    #pragma unroll
    for (int ks = 0; ks < 20; ks++){
        const int k0 = ks*8;
        afr[ks][0] = __float_as_uint(sAh[(m0+g  )*164 + k0 + t    ]);
        afr[ks][1] = __float_as_uint(sAh[(m0+g+8)*164 + k0 + t    ]);
        afr[ks][2] = __float_as_uint(sAh[(m0+g  )*164 + k0 + t + 4]);
        afr[ks][3] = __float_as_uint(sAh[(m0+g+8)*164 + k0 + t + 4]);
    }

    float hm[20][4];
    #pragma unroll
    for (int n2 = 0; n2 < 20; n2++)
        #pragma unroll
        for (int k = 0; k < 4; k++) hm[n2][k] = 0.f;
    float lr0 = 0.f, lr1 = 0.f;

    #pragma unroll 1
    for (int c = 0; c < 64; c++){
        const int p = c & 1;
        CP_WAIT1();
        __syncthreads();

        const float* QWb  = sQW  + p*(32*164);
        const float* QhTb = sQhT + p*(160*36);

        // ---- GEMM1: S chunk [16 x 32], K=160, paired LDS.64 B ----
        float sc[4][4];
        #pragma unroll
        for (int nt = 0; nt < 4; nt++)
            #pragma unroll
            for (int k = 0; k < 4; k++) sc[nt][k] = 0.f;

        #pragma unroll
        for (int ks = 0; ks < 20; ks++){
            const int k0 = ks*8;
            #pragma unroll
            for (int nt = 0; nt < 4; nt++){
                ull bv = *(const ull*)&QWb[(nt*8+g)*164 + k0 + 2*t];
                mma1688(sc[nt], afr[ks], (uint32_t)bv, (uint32_t)(bv >> 32));
            }
        }

        // ---- softmax numerator (no max) + row sums ----
        float pv[4][4];
        float rs0 = 0.f, rs1 = 0.f;
        #pragma unroll
        for (int nt = 0; nt < 4; nt++){
            pv[nt][0] = __expf(sc[nt][0]);
            pv[nt][1] = __expf(sc[nt][1]);
            pv[nt][2] = __expf(sc[nt][2]);
            pv[nt][3] = __expf(sc[nt][3]);
            rs0 += pv[nt][0] + pv[nt][1];
            rs1 += pv[nt][2] + pv[nt][3];
        }
        rs0 += __shfl_xor_sync(0xffffffffu, rs0, 1);
        rs0 += __shfl_xor_sync(0xffffffffu, rs0, 2);
        rs1 += __shfl_xor_sync(0xffffffffu, rs1, 1);
        rs1 += __shfl_xor_sync(0xffffffffu, rs1, 2);
        lr0 += rs0; lr1 += rs1;

        // ---- P: C-frag -> A-frag via quad shfl ----
        uint32_t pa[4][4];
        const int qs  = (lane & ~3) | (t >> 1);
        const int qs2 = qs | 2;
        const bool odd = (t & 1);
        #pragma unroll
        for (int nt = 0; nt < 4; nt++){
            float x0 = __shfl_sync(0xffffffffu, pv[nt][0], qs);
            float x1 = __shfl_sync(0xffffffffu, pv[nt][1], qs);
            float x2 = __shfl_sync(0xffffffffu, pv[nt][2], qs);
            float x3 = __shfl_sync(0xffffffffu, pv[nt][3], qs);
            float y0 = __shfl_sync(0xffffffffu, pv[nt][0], qs2);
            float y1 = __shfl_sync(0xffffffffu, pv[nt][1], qs2);
            float y2 = __shfl_sync(0xffffffffu, pv[nt][2], qs2);
            float y3 = __shfl_sync(0xffffffffu, pv[nt][3], qs2);
            pa[nt][0] = rtfu(odd ? x1 : x0);
            pa[nt][1] = rtfu(odd ? x3 : x2);
            pa[nt][2] = rtfu(odd ? y1 : y0);
            pa[nt][3] = rtfu(odd ? y3 : y2);
        }

        // ---- GEMM2: Hm[16 x 160] += P @ QhT^T, paired LDS.64 B ----
        #pragma unroll
        for (int kt = 0; kt < 4; kt++){
            const int k0 = kt*8;
            #pragma unroll
            for (int n2 = 0; n2 < 20; n2++){
                ull bv = *(const ull*)&QhTb[(n2*8+g)*36 + k0 + 2*t];
                mma1688(hm[n2], pa[kt], (uint32_t)bv, (uint32_t)(bv >> 32));
            }
        }

        __syncthreads();
        if (c + 2 < 64) stageQ(c+2, p);
        CP_COMMIT();
    }

    const float inv0 = 1.f / lr0, inv1 = 1.f / lr1;
    float* __restrict__ H0 = g_Hm + ((size_t)b*LSEQ + a0 + m0 + g    )*HSP;
    float* __restrict__ H1 = g_Hm + ((size_t)b*LSEQ + a0 + m0 + g + 8)*HSP;
    #pragma unroll
    for (int n2 = 0; n2 < 20; n2++){
        const int col = n2*8 + 2*t;
        *(float2*)(H0 + col) = make_float2(hm[n2][0]*inv0, hm[n2][1]*inv0);
        *(float2*)(H1 + col) = make_float2(hm[n2][2]*inv1, hm[n2][3]*inv1);
    }
}

// =====================================================================
// Kernel 5: T = relu([Ah | Hm] @ WtT + bt) (mma tf32)
// =====================================================================
#define OT_ABUF 2304
#define OT_BBUF 5760
#define OT_SMEM ((2*OT_ABUF + 2*OT_BBUF)*4)

__global__ void __launch_bounds__(256) out_tc_kernel(
    const float* __restrict__ bt, float* __restrict__ out)
{
    extern __shared__ __align__(16) float smem[];
    float* As = smem;
    float* Bs = smem + 2*OT_ABUF;

    const int tid = threadIdx.x, lane = tid & 31, wid = tid >> 5;
    const int wm = wid & 1, wn = wid >> 1;
    const int g = lane >> 2, t = lane & 3;
    const int row0 = blockIdx.x * 64;

    const uint32_t sA = smem_u32(As);
    const uint32_t sB = smem_u32(Bs);

    float acc[2][5][4];
    #pragma unroll
    for (int i = 0; i < 2; i++)
        #pragma unroll
        for (int n = 0; n < 5; n++)
            #pragma unroll
            for (int k = 0; k < 4; k++) acc[i][n][k] = 0.f;

    auto stage = [&](int c, int buf){
        const int kc = c*32;
        const float* __restrict__ Sp = (c < 5)
            ? (g_Ah + (size_t)row0*HSP + kc)
            : (g_Hm + (size_t)row0*HSP + (kc - 160));
        #pragma unroll
        for (int i = 0; i < 2; i++){
            int idx = tid + i*256;
            int r = idx >> 3, kq = idx & 7;
            cp16(sA + (uint32_t)(buf*OT_ABUF + r*36 + kq*4)*4,
                 Sp + (size_t)r*HSP + kq*4);
        }
        #pragma unroll
        for (int i = 0; i < 5; i++){
            int idx = tid + i*256;
            int r = idx >> 3, kq = idx & 7;
            cp16(sB + (uint32_t)(buf*OT_BBUF + r*36 + kq*4)*4,
                 g_WtT + r*320 + kc + kq*4);
        }
    };

    stage(0, 0); CP_COMMIT();

    #pragma unroll 1
    for (int c = 0; c < 10; c++){
        if (c + 1 < 10) stage(c+1, (c+1)&1);
        CP_COMMIT();
        CP_WAIT1();
        __syncthreads();

        const float* Ab = As + (c&1)*OT_ABUF;
        const float* Bb = Bs + (c&1)*OT_BBUF;
        #pragma unroll
        for (int k0 = 0; k0 < 32; k0 += 8){
            uint32_t afr[2][4];
            #pragma unroll
            for (int mt = 0; mt < 2; mt++){
                const int m = wm*32 + mt*16;
                afr[mt][0] = rtfu(Ab[(m+g  )*36 + k0 + t    ]);
                afr[mt][1] = rtfu(Ab[(m+g+8)*36 + k0 + t    ]);
                afr[mt][2] = rtfu(Ab[(m+g  )*36 + k0 + t + 4]);
                afr[mt][3] = rtfu(Ab[(m+g+8)*36 + k0 + t + 4]);
            }
            #pragma unroll
            for (int nt = 0; nt < 5; nt++){
                const int n = wn*40 + nt*8;
                uint32_t b0 = __float_as_uint(Bb[(n+g)*36 + k0 + t    ]);
                uint32_t b1 = __float_as_uint(Bb[(n+g)*36 + k0 + t + 4]);
                mma1688(acc[0][nt], afr[0], b0, b1);
                mma1688(acc[1][nt], afr[1], b0, b1);
            }
        }
        __syncthreads();
    }

    #pragma unroll
    for (int mt = 0; mt < 2; mt++){
        #pragma unroll
        for (int j2 = 0; j2 < 2; j2++){
            const int r = row0 + wm*32 + mt*16 + g + j2*8;
            #pragma unroll
            for (int nt = 0; nt < 5; nt++){
                const int ncol = wn*40 + nt*8 + 2*t;
                if (ncol < HH){
                    float v0 = fmaxf(acc[mt][nt][2*j2    ] + __ldg(bt + ncol),     0.f);
                    float v1 = fmaxf(acc[mt][nt][2*j2 + 1] + __ldg(bt + ncol + 1), 0.f);
                    *(float2*)(out + (size_t)r*HH + ncol) = make_float2(v0, v1);
                }
            }
        }
    }
}

// =====================================================================
extern "C" void kernel_launch(void* const* d_in, const int* in_sizes, int n_in,
                              void* d_out, int out_size)
{
    (void)in_sizes; (void)n_in; (void)out_size;
    const float* Q  = (const float*)d_in[0];
    const float* A  = (const float*)d_in[1];
    const float* Wi = (const float*)d_in[2];
    const float* Wu = (const float*)d_in[3];
    const float* Wg = (const float*)d_in[4];
    const float* Wt = (const float*)d_in[5];
    const float* bi = (const float*)d_in[6];
    const float* bu = (const float*)d_in[7];
    const float* bg = (const float*)d_in[8];
    const float* bt = (const float*)d_in[9];
    float* out = (float*)d_out;

    static bool attr_done = false;
    if (!attr_done){
        cudaFuncSetAttribute(gate_tc_kernel<true >, cudaFuncAttributeMaxDynamicSharedMemorySize, GT_SMEM);
        cudaFuncSetAttribute(gate_tc_kernel<false>, cudaFuncAttributeMaxDynamicSharedMemorySize, GT_SMEM);
        cudaFuncSetAttribute(flash_kernel,  cudaFuncAttributeMaxDynamicSharedMemorySize, FL_SMEM);
        cudaFuncSetAttribute(out_tc_kernel, cudaFuncAttributeMaxDynamicSharedMemorySize, OT_SMEM);
        attr_done = true;
    }

    prep_kernel<<<400, 256>>>(Wi, Wu, Wg, Wt);
    gate_tc_kernel<true ><<<NRTOT/64, 256, GT_SMEM>>>(Q, bi, bu, bg);
    gate_tc_kernel<false><<<NRTOT/64, 256, GT_SMEM>>>(A, bi, bu, bg);
    flash_kernel<<<dim3(LSEQ/128, BATCH), 256, FL_SMEM>>>();
    out_tc_kernel<<<NRTOT/64, 256, OT_SMEM>>>(bt, out);
}

// round 13
// speedup vs baseline: 1.0457x; 1.0457x over previous
#include <cuda_runtime.h>
#include <cstdint>
#include <math.h>

#define BATCH 8
#define LSEQ  2048
#define DIM   300
#define HH    150
#define HSP   160
#define NRTOT (BATCH*LSEQ)

typedef unsigned long long ull;

__device__ __forceinline__ float rtf(float x){
    uint32_t r; asm("cvt.rna.tf32.f32 %0, %1;" : "=r"(r) : "f"(x));
    return __uint_as_float(r);
}
__device__ __forceinline__ uint32_t rtfu(float x){
    uint32_t r; asm("cvt.rna.tf32.f32 %0, %1;" : "=r"(r) : "f"(x));
    return r;
}
__device__ __forceinline__ uint32_t smem_u32(const void* p){
    uint32_t a; asm("{ .reg .u64 t; cvta.to.shared.u64 t, %1; cvt.u32.u64 %0, t; }" : "=r"(a) : "l"(p));
    return a;
}
__device__ __forceinline__ void mma1688(float* c, const uint32_t* a, uint32_t b0, uint32_t b1){
    asm volatile(
        "mma.sync.aligned.m16n8k8.row.col.f32.tf32.tf32.f32 "
        "{%0,%1,%2,%3}, {%4,%5,%6,%7}, {%8,%9}, {%0,%1,%2,%3};"
        : "+f"(c[0]), "+f"(c[1]), "+f"(c[2]), "+f"(c[3])
        : "r"(a[0]), "r"(a[1]), "r"(a[2]), "r"(a[3]), "r"(b0), "r"(b1));
}
__device__ __forceinline__ void cp16(uint32_t smem_addr, const void* gptr){
    asm volatile("cp.async.cg.shared.global [%0], [%1], 16;" :: "r"(smem_addr), "l"(gptr));
}
__device__ __forceinline__ void cp16z(uint32_t smem_addr, const void* gptr, uint32_t srcb){
    asm volatile("cp.async.cg.shared.global [%0], [%1], 16, %2;" :: "r"(smem_addr), "l"(gptr), "r"(srcb));
}
#define CP_COMMIT() asm volatile("cp.async.commit_group;" ::: "memory")
#define CP_WAIT1()  asm volatile("cp.async.wait_group 1;"  ::: "memory")
#define CP_WAIT0()  asm volatile("cp.async.wait_group 0;"  ::: "memory")

// ---------------- scratch ----------------
__device__ __align__(16) float g_QW [NRTOT*HSP];
__device__ __align__(16) float g_QhT[BATCH*HSP*LSEQ];
__device__ __align__(16) float g_Ah [NRTOT*HSP];
__device__ __align__(16) float g_Hm [NRTOT*HSP];
__device__ __align__(16) float g_Wcat[320*320];
__device__ __align__(16) float g_WgT [160*160];
__device__ __align__(16) float g_WtT [160*320];

// =====================================================================
// Kernel 0: weight prep
// =====================================================================
__global__ void __launch_bounds__(256) prep_kernel(
    const float* __restrict__ Wi, const float* __restrict__ Wu,
    const float* __restrict__ Wg, const float* __restrict__ Wt)
{
    int idx = blockIdx.x*256 + threadIdx.x;
    if (idx < 320*320){
        int n = idx / 320, k = idx - n*320;
        float v = 0.f;
        if (k < 300){
            if (n < 150)                  v = Wi[k*HH + n];
            else if (n >= 160 && n < 310) v = Wu[k*HH + (n-160)];
        }
        g_Wcat[idx] = rtf(v);
    }
    if (idx < 160*160){
        int n = idx / 160, k = idx - n*160;
        float v = (n < 150 && k < 150) ? Wg[k*HH + n] : 0.f;
        g_WgT[idx] = rtf(v);
    }
    if (idx < 160*320){
        int n = idx / 320, k = idx - n*320;
        float v = 0.f;
        if (n < 150){
            if (k < 150)                  v = Wt[k*HH + n];
            else if (k >= 160 && k < 310) v = Wt[(k - 160 + 150)*HH + n];
        }
        g_WtT[idx] = rtf(v);
    }
}

// =====================================================================
// Kernel 1: gate projections (mma tf32) + fused QW GEMM for the Q path.
// =====================================================================
#define GT_ABUF 2304
#define GT_BBUF 11520
#define GT_SMEM ((2*GT_ABUF + 2*GT_BBUF)*4)

template<bool IS_Q>
__global__ void __launch_bounds__(256) gate_tc_kernel(
    const float* __restrict__ X,
    const float* __restrict__ bi, const float* __restrict__ bu,
    const float* __restrict__ bg)
{
    extern __shared__ __align__(16) float smem[];
    float* As = smem;
    float* Bs = smem + 2*GT_ABUF;

    const int tid = threadIdx.x, lane = tid & 31, wid = tid >> 5;
    const int wm = wid & 1, wn = wid >> 1;
    const int g = lane >> 2, t = lane & 3;
    const int row0 = blockIdx.x * 64;

    const float* __restrict__ Ap = X + (size_t)row0*DIM;
    const uint32_t sA = smem_u32(As);
    const uint32_t sB = smem_u32(Bs);

    float acc[2][10][4];
    #pragma unroll
    for (int i = 0; i < 2; i++)
        #pragma unroll
        for (int n = 0; n < 10; n++)
            #pragma unroll
            for (int k = 0; k < 4; k++) acc[i][n][k] = 0.f;

    auto stage = [&](int c, int buf){
        const int kc = c*32;
        #pragma unroll
        for (int i = 0; i < 2; i++){
            int idx = tid + i*256;
            int r = idx >> 3, kq = idx & 7;
            int gk = kc + kq*4;
            uint32_t srcb = (gk + 4 <= DIM) ? 16u : 0u;
            const float* src = srcb ? (Ap + (size_t)r*DIM + gk) : Ap;
            cp16z(sA + (uint32_t)(buf*GT_ABUF + r*36 + kq*4)*4, src, srcb);
        }
        #pragma unroll
        for (int i = 0; i < 10; i++){
            int idx = tid + i*256;
            int r = idx >> 3, kq = idx & 7;
            cp16(sB + (uint32_t)(buf*GT_BBUF + r*36 + kq*4)*4,
                 g_Wcat + r*320 + kc + kq*4);
        }
    };

    stage(0, 0); CP_COMMIT();

    #pragma unroll 1
    for (int c = 0; c < 10; c++){
        if (c + 1 < 10) stage(c+1, (c+1)&1);
        CP_COMMIT();
        CP_WAIT1();
        __syncthreads();

        const float* Ab = As + (c&1)*GT_ABUF;
        const float* Bb = Bs + (c&1)*GT_BBUF;
        #pragma unroll
        for (int k0 = 0; k0 < 32; k0 += 8){
            uint32_t afr[2][4];
            #pragma unroll
            for (int mt = 0; mt < 2; mt++){
                const int m = wm*32 + mt*16;
                afr[mt][0] = rtfu(Ab[(m+g  )*36 + k0 + t    ]);
                afr[mt][1] = rtfu(Ab[(m+g+8)*36 + k0 + t    ]);
                afr[mt][2] = rtfu(Ab[(m+g  )*36 + k0 + t + 4]);
                afr[mt][3] = rtfu(Ab[(m+g+8)*36 + k0 + t + 4]);
            }
            #pragma unroll
            for (int nt = 0; nt < 10; nt++){
                const int n = (nt < 5) ? (wn*40 + nt*8) : (160 + wn*40 + (nt-5)*8);
                uint32_t b0 = __float_as_uint(Bb[(n+g)*36 + k0 + t    ]);
                uint32_t b1 = __float_as_uint(Bb[(n+g)*36 + k0 + t + 4]);
                mma1688(acc[0][nt], afr[0], b0, b1);
                mma1688(acc[1][nt], afr[1], b0, b1);
            }
        }
        __syncthreads();
    }
    __syncthreads();

    #pragma unroll
    for (int mt = 0; mt < 2; mt++){
        #pragma unroll
        for (int j2 = 0; j2 < 2; j2++){
            const int rl = wm*32 + mt*16 + g + j2*8;
            const int r  = row0 + rl;
            const int b = r >> 11, q = r & (LSEQ-1);
            #pragma unroll
            for (int ntp = 0; ntp < 5; ntp++){
                const int ncol = wn*40 + ntp*8 + 2*t;
                float h0 = 0.f, h1 = 0.f;
                if (ncol < HH){
                    float xi0 = acc[mt][ntp  ][2*j2    ] + __ldg(bi + ncol);
                    float xi1 = acc[mt][ntp  ][2*j2 + 1] + __ldg(bi + ncol + 1);
                    float xu0 = acc[mt][ntp+5][2*j2    ] + __ldg(bu + ncol);
                    float xu1 = acc[mt][ntp+5][2*j2 + 1] + __ldg(bu + ncol + 1);
                    h0 = rtf((1.f/(1.f + __expf(-xi0))) * tanhf(xu0));
                    h1 = rtf((1.f/(1.f + __expf(-xi1))) * tanhf(xu1));
                }
                if (IS_Q){
                    *(float2*)(Bs + rl*164 + ncol) = make_float2(h0, h1);
                    g_QhT[((size_t)b*HSP + ncol    )*LSEQ + q] = h0;
                    g_QhT[((size_t)b*HSP + ncol + 1)*LSEQ + q] = h1;
                } else {
                    *(float2*)(g_Ah + (size_t)r*HSP + ncol) = make_float2(h0, h1);
                }
            }
        }
    }

    if (IS_Q){
        const float* qhS = Bs;
        float* wgS = Bs + 10496;
        const uint32_t sWg = smem_u32(wgS);

        float acc2[2][5][4];
        #pragma unroll
        for (int i = 0; i < 2; i++)
            #pragma unroll
            for (int n = 0; n < 5; n++)
                #pragma unroll
                for (int k = 0; k < 4; k++) acc2[i][n][k] = 0.f;

        auto stageW = [&](int c, int buf){
            const int kc = c*32;
            #pragma unroll
            for (int i = 0; i < 5; i++){
                int idx = tid + i*256;
                int r = idx >> 3, kq = idx & 7;
                cp16(sWg + (uint32_t)(buf*5760 + r*36 + kq*4)*4,
                     g_WgT + r*160 + kc + kq*4);
            }
        };
        stageW(0, 0); CP_COMMIT();

        #pragma unroll 1
        for (int c = 0; c < 5; c++){
            if (c + 1 < 5) stageW(c+1, (c+1)&1);
            CP_COMMIT();
            CP_WAIT1();
            __syncthreads();

            const float* Wb = wgS + (c&1)*5760;
            #pragma unroll
            for (int k0 = 0; k0 < 32; k0 += 8){
                const int kk = c*32 + k0;
                uint32_t af[2][4];
                #pragma unroll
                for (int mt = 0; mt < 2; mt++){
                    const int m = wm*32 + mt*16;
                    af[mt][0] = __float_as_uint(qhS[(m+g  )*164 + kk + t    ]);
                    af[mt][1] = __float_as_uint(qhS[(m+g+8)*164 + kk + t    ]);
                    af[mt][2] = __float_as_uint(qhS[(m+g  )*164 + kk + t + 4]);
                    af[mt][3] = __float_as_uint(qhS[(m+g+8)*164 + kk + t + 4]);
                }
                #pragma unroll
                for (int nt = 0; nt < 5; nt++){
                    const int n = wn*40 + nt*8;
                    uint32_t b0 = __float_as_uint(Wb[(n+g)*36 + k0 + t    ]);
                    uint32_t b1 = __float_as_uint(Wb[(n+g)*36 + k0 + t + 4]);
                    mma1688(acc2[0][nt], af[0], b0, b1);
                    mma1688(acc2[1][nt], af[1], b0, b1);
                }
            }
            __syncthreads();
        }

        #pragma unroll
        for (int mt = 0; mt < 2; mt++){
            #pragma unroll
            for (int j2 = 0; j2 < 2; j2++){
                const int r = row0 + wm*32 + mt*16 + g + j2*8;
                #pragma unroll
                for (int nt = 0; nt < 5; nt++){
                    const int ncol = wn*40 + nt*8 + 2*t;
                    float v0 = 0.f, v1 = 0.f;
                    if (ncol < HH){
                        v0 = rtf(acc2[mt][nt][2*j2    ] + __ldg(bg + ncol));
                        v1 = rtf(acc2[mt][nt][2*j2 + 1] + __ldg(bg + ncol + 1));
                    }
                    *(float2*)(g_QW + (size_t)r*HSP + ncol) = make_float2(v0, v1);
                }
            }
        }
    }
}

// =====================================================================
// Kernel 2 (flash): R10 inner loop, 64-row CTA, 128 threads (4 warps),
// q-chunks of 32, A-frags hoisted, no-max softmax. Smem 88KB with the
// Ah tile staged into the buffer region (prologue-only) -> 2 CTAs/SM.
// =====================================================================
#define FL_QW_SZ   5248                    // 32*164 floats
#define FL_QHT_SZ  5760                    // 160*36 floats
#define FL_QHT_OFF (2*FL_QW_SZ)            // 10496
#define FL_SMEM    ((2*FL_QW_SZ + 2*FL_QHT_SZ)*4)   // 88064 bytes

__global__ void __launch_bounds__(128, 2) flash_kernel()
{
    extern __shared__ __align__(16) float smem[];
    float* sAh  = smem;                  // [64][164]  (prologue only, overlaps buffers)
    float* sQW  = smem;                  // [2][32][164]
    float* sQhT = smem + FL_QHT_OFF;     // [2][160][36]

    const int tid = threadIdx.x, lane = tid & 31, w = tid >> 5;
    const int g = lane >> 2, t = lane & 3;
    const int b = blockIdx.y, a0 = blockIdx.x*64;
    const int m0 = w*16;

    const uint32_t sbAh  = smem_u32(sAh);
    const uint32_t sbQW  = smem_u32(sQW);
    const uint32_t sbQhT = smem_u32(sQhT);

    const float* __restrict__ AhP  = g_Ah  + ((size_t)b*LSEQ + a0)*HSP;
    const float* __restrict__ QWP  = g_QW  + (size_t)b*LSEQ*HSP;
    const float* __restrict__ QhTP = g_QhT + (size_t)b*HSP*LSEQ;

    // ---- prologue: stage Ah into (to-be-reused) buffer region ----
    #pragma unroll
    for (int i = 0; i < 20; i++){
        int idx = tid + i*128;
        int r = idx / 40, kq = idx - r*40;
        cp16(sbAh + (uint32_t)(r*164 + kq*4)*4, AhP + (size_t)r*HSP + kq*4);
    }
    CP_COMMIT();
    CP_WAIT0();
    __syncthreads();

    uint32_t afr[20][4];
    #pragma unroll
    for (int ks = 0; ks < 20; ks++){
        const int k0 = ks*8;
        afr[ks][0] = __float_as_uint(sAh[(m0+g  )*164 + k0 + t    ]);
        afr[ks][1] = __float_as_uint(sAh[(m0+g+8)*164 + k0 + t    ]);
        afr[ks][2] = __float_as_uint(sAh[(m0+g  )*164 + k0 + t + 4]);
        afr[ks][3] = __float_as_uint(sAh[(m0+g+8)*164 + k0 + t + 4]);
    }
    __syncthreads();   // everyone done with Ah; buffers may be overwritten

    auto stageQ = [&](int c, int buf){
        const int qc = c*32;
        #pragma unroll
        for (int i = 0; i < 10; i++){
            int idx = tid + i*128;
            int r = idx / 40, kq = idx - r*40;
            cp16(sbQW + (uint32_t)(buf*FL_QW_SZ + r*164 + kq*4)*4,
                 QWP + (size_t)(qc + r)*HSP + kq*4);
        }
        #pragma unroll
        for (int i = 0; i < 10; i++){
            int idx = tid + i*128;
            int r = idx >> 3, qq = idx & 7;
            cp16(sbQhT + (uint32_t)(buf*FL_QHT_SZ + r*36 + qq*4)*4,
                 QhTP + (size_t)r*LSEQ + qc + qq*4);
        }
    };
    stageQ(0, 0); CP_COMMIT();
    stageQ(1, 1); CP_COMMIT();

    float hm[20][4];
    #pragma unroll
    for (int n2 = 0; n2 < 20; n2++)
        #pragma unroll
        for (int k = 0; k < 4; k++) hm[n2][k] = 0.f;
    float lr0 = 0.f, lr1 = 0.f;

    #pragma unroll 1
    for (int c = 0; c < 64; c++){
        const int p = c & 1;
        CP_WAIT1();
        __syncthreads();

        const float* QWb  = sQW  + p*FL_QW_SZ;
        const float* QhTb = sQhT + p*FL_QHT_SZ;

        // ---- GEMM1: S chunk [16 rows x 32 q], K=160 ----
        float sc[4][4];
        #pragma unroll
        for (int nt = 0; nt < 4; nt++)
            #pragma unroll
            for (int k = 0; k < 4; k++) sc[nt][k] = 0.f;

        #pragma unroll
        for (int ks = 0; ks < 20; ks++){
            const int k0 = ks*8;
            #pragma unroll
            for (int nt = 0; nt < 4; nt++){
                uint32_t b0 = __float_as_uint(QWb[(nt*8+g)*164 + k0 + t    ]);
                uint32_t b1 = __float_as_uint(QWb[(nt*8+g)*164 + k0 + t + 4]);
                mma1688(sc[nt], afr[ks], b0, b1);
            }
        }

        // ---- softmax numerator (no max shift) + row sums ----
        float pv[4][4];
        float rs0 = 0.f, rs1 = 0.f;
        #pragma unroll
        for (int nt = 0; nt < 4; nt++){
            pv[nt][0] = __expf(sc[nt][0]);
            pv[nt][1] = __expf(sc[nt][1]);
            pv[nt][2] = __expf(sc[nt][2]);
            pv[nt][3] = __expf(sc[nt][3]);
            rs0 += pv[nt][0] + pv[nt][1];
            rs1 += pv[nt][2] + pv[nt][3];
        }
        rs0 += __shfl_xor_sync(0xffffffffu, rs0, 1);
        rs0 += __shfl_xor_sync(0xffffffffu, rs0, 2);
        rs1 += __shfl_xor_sync(0xffffffffu, rs1, 1);
        rs1 += __shfl_xor_sync(0xffffffffu, rs1, 2);
        lr0 += rs0; lr1 += rs1;

        // ---- P: C-frag -> A-frag via quad shfl ----
        uint32_t pa[4][4];
        const int qs  = (lane & ~3) | (t >> 1);
        const int qs2 = qs | 2;
        const bool odd = (t & 1);
        #pragma unroll
        for (int nt = 0; nt < 4; nt++){
            float x0 = __shfl_sync(0xffffffffu, pv[nt][0], qs);
            float x1 = __shfl_sync(0xffffffffu, pv[nt][1], qs);
            float x2 = __shfl_sync(0xffffffffu, pv[nt][2], qs);
            float x3 = __shfl_sync(0xffffffffu, pv[nt][3], qs);
            float y0 = __shfl_sync(0xffffffffu, pv[nt][0], qs2);
            float y1 = __shfl_sync(0xffffffffu, pv[nt][1], qs2);
            float y2 = __shfl_sync(0xffffffffu, pv[nt][2], qs2);
            float y3 = __shfl_sync(0xffffffffu, pv[nt][3], qs2);
            pa[nt][0] = rtfu(odd ? x1 : x0);
            pa[nt][1] = rtfu(odd ? x3 : x2);
            pa[nt][2] = rtfu(odd ? y1 : y0);
            pa[nt][3] = rtfu(odd ? y3 : y2);
        }

        // ---- GEMM2: Hm[16 x 160] += P[16 x 32] @ QhT^T ----
        #pragma unroll
        for (int nt = 0; nt < 4; nt++){
            const int k0 = nt*8;
            #pragma unroll
            for (int n2 = 0; n2 < 20; n2++){
                uint32_t b0 = __float_as_uint(QhTb[(n2*8+g)*36 + k0 + t    ]);
                uint32_t b1 = __float_as_uint(QhTb[(n2*8+g)*36 + k0 + t + 4]);
                mma1688(hm[n2], pa[nt], b0, b1);
            }
        }

        __syncthreads();
        if (c + 2 < 64) stageQ(c+2, p);
        CP_COMMIT();
    }

    const float inv0 = 1.f / lr0, inv1 = 1.f / lr1;
    float* __restrict__ H0 = g_Hm + ((size_t)b*LSEQ + a0 + m0 + g    )*HSP;
    float* __restrict__ H1 = g_Hm + ((size_t)b*LSEQ + a0 + m0 + g + 8)*HSP;
    #pragma unroll
    for (int n2 = 0; n2 < 20; n2++){
        const int col = n2*8 + 2*t;
        *(float2*)(H0 + col) = make_float2(hm[n2][0]*inv0, hm[n2][1]*inv0);
        *(float2*)(H1 + col) = make_float2(hm[n2][2]*inv1, hm[n2][3]*inv1);
    }
}

// =====================================================================
// Kernel 5: T = relu([Ah | Hm] @ WtT + bt) (mma tf32)
// =====================================================================
#define OT_ABUF 2304
#define OT_BBUF 5760
#define OT_SMEM ((2*OT_ABUF + 2*OT_BBUF)*4)

__global__ void __launch_bounds__(256) out_tc_kernel(
    const float* __restrict__ bt, float* __restrict__ out)
{
    extern __shared__ __align__(16) float smem[];
    float* As = smem;
    float* Bs = smem + 2*OT_ABUF;

    const int tid = threadIdx.x, lane = tid & 31, wid = tid >> 5;
    const int wm = wid & 1, wn = wid >> 1;
    const int g = lane >> 2, t = lane & 3;
    const int row0 = blockIdx.x * 64;

    const uint32_t sA = smem_u32(As);
    const uint32_t sB = smem_u32(Bs);

    float acc[2][5][4];
    #pragma unroll
    for (int i = 0; i < 2; i++)
        #pragma unroll
        for (int n = 0; n < 5; n++)
            #pragma unroll
            for (int k = 0; k < 4; k++) acc[i][n][k] = 0.f;

    auto stage = [&](int c, int buf){
        const int kc = c*32;
        const float* __restrict__ Sp = (c < 5)
            ? (g_Ah + (size_t)row0*HSP + kc)
            : (g_Hm + (size_t)row0*HSP + (kc - 160));
        #pragma unroll
        for (int i = 0; i < 2; i++){
            int idx = tid + i*256;
            int r = idx >> 3, kq = idx & 7;
            cp16(sA + (uint32_t)(buf*OT_ABUF + r*36 + kq*4)*4,
                 Sp + (size_t)r*HSP + kq*4);
        }
        #pragma unroll
        for (int i = 0; i < 5; i++){
            int idx = tid + i*256;
            int r = idx >> 3, kq = idx & 7;
            cp16(sB + (uint32_t)(buf*OT_BBUF + r*36 + kq*4)*4,
                 g_WtT + r*320 + kc + kq*4);
        }
    };

    stage(0, 0); CP_COMMIT();

    #pragma unroll 1
    for (int c = 0; c < 10; c++){
        if (c + 1 < 10) stage(c+1, (c+1)&1);
        CP_COMMIT();
        CP_WAIT1();
        __syncthreads();

        const float* Ab = As + (c&1)*OT_ABUF;
        const float* Bb = Bs + (c&1)*OT_BBUF;
        #pragma unroll
        for (int k0 = 0; k0 < 32; k0 += 8){
            uint32_t afr[2][4];
            #pragma unroll
            for (int mt = 0; mt < 2; mt++){
                const int m = wm*32 + mt*16;
                afr[mt][0] = rtfu(Ab[(m+g  )*36 + k0 + t    ]);
                afr[mt][1] = rtfu(Ab[(m+g+8)*36 + k0 + t    ]);
                afr[mt][2] = rtfu(Ab[(m+g  )*36 + k0 + t + 4]);
                afr[mt][3] = rtfu(Ab[(m+g+8)*36 + k0 + t + 4]);
            }
            #pragma unroll
            for (int nt = 0; nt < 5; nt++){
                const int n = wn*40 + nt*8;
                uint32_t b0 = __float_as_uint(Bb[(n+g)*36 + k0 + t    ]);
                uint32_t b1 = __float_as_uint(Bb[(n+g)*36 + k0 + t + 4]);
                mma1688(acc[0][nt], afr[0], b0, b1);
                mma1688(acc[1][nt], afr[1], b0, b1);
            }
        }
        __syncthreads();
    }

    #pragma unroll
    for (int mt = 0; mt < 2; mt++){
        #pragma unroll
        for (int j2 = 0; j2 < 2; j2++){
            const int r = row0 + wm*32 + mt*16 + g + j2*8;
            #pragma unroll
            for (int nt = 0; nt < 5; nt++){
                const int ncol = wn*40 + nt*8 + 2*t;
                if (ncol < HH){
                    float v0 = fmaxf(acc[mt][nt][2*j2    ] + __ldg(bt + ncol),     0.f);
                    float v1 = fmaxf(acc[mt][nt][2*j2 + 1] + __ldg(bt + ncol + 1), 0.f);
                    *(float2*)(out + (size_t)r*HH + ncol) = make_float2(v0, v1);
                }
            }
        }
    }
}

// =====================================================================
extern "C" void kernel_launch(void* const* d_in, const int* in_sizes, int n_in,
                              void* d_out, int out_size)
{
    (void)in_sizes; (void)n_in; (void)out_size;
    const float* Q  = (const float*)d_in[0];
    const float* A  = (const float*)d_in[1];
    const float* Wi = (const float*)d_in[2];
    const float* Wu = (const float*)d_in[3];
    const float* Wg = (const float*)d_in[4];
    const float* Wt = (const float*)d_in[5];
    const float* bi = (const float*)d_in[6];
    const float* bu = (const float*)d_in[7];
    const float* bg = (const float*)d_in[8];
    const float* bt = (const float*)d_in[9];
    float* out = (float*)d_out;

    static bool attr_done = false;
    if (!attr_done){
        cudaFuncSetAttribute(gate_tc_kernel<true >, cudaFuncAttributeMaxDynamicSharedMemorySize, GT_SMEM);
        cudaFuncSetAttribute(gate_tc_kernel<false>, cudaFuncAttributeMaxDynamicSharedMemorySize, GT_SMEM);
        cudaFuncSetAttribute(flash_kernel,  cudaFuncAttributeMaxDynamicSharedMemorySize, FL_SMEM);
        cudaFuncSetAttribute(out_tc_kernel, cudaFuncAttributeMaxDynamicSharedMemorySize, OT_SMEM);
        attr_done = true;
    }

    prep_kernel<<<400, 256>>>(Wi, Wu, Wg, Wt);
    gate_tc_kernel<true ><<<NRTOT/64, 256, GT_SMEM>>>(Q, bi, bu, bg);
    gate_tc_kernel<false><<<NRTOT/64, 256, GT_SMEM>>>(A, bi, bu, bg);
    flash_kernel<<<dim3(LSEQ/64, BATCH), 128, FL_SMEM>>>();
    out_tc_kernel<<<NRTOT/64, 256, OT_SMEM>>>(bt, out);
}

// round 14
// speedup vs baseline: 1.2869x; 1.2307x over previous
#include <cuda_runtime.h>
#include <cstdint>
#include <math.h>

#define BATCH 8
#define LSEQ  2048
#define DIM   300
#define HH    150
#define HSP   160
#define NRTOT (BATCH*LSEQ)

typedef unsigned long long ull;

__device__ __forceinline__ float rtf(float x){
    uint32_t r; asm("cvt.rna.tf32.f32 %0, %1;" : "=r"(r) : "f"(x));
    return __uint_as_float(r);
}
__device__ __forceinline__ uint32_t rtfu(float x){
    uint32_t r; asm("cvt.rna.tf32.f32 %0, %1;" : "=r"(r) : "f"(x));
    return r;
}
__device__ __forceinline__ uint32_t smem_u32(const void* p){
    uint32_t a; asm("{ .reg .u64 t; cvta.to.shared.u64 t, %1; cvt.u32.u64 %0, t; }" : "=r"(a) : "l"(p));
    return a;
}
__device__ __forceinline__ void mma1688(float* c, const uint32_t* a, uint32_t b0, uint32_t b1){
    asm volatile(
        "mma.sync.aligned.m16n8k8.row.col.f32.tf32.tf32.f32 "
        "{%0,%1,%2,%3}, {%4,%5,%6,%7}, {%8,%9}, {%0,%1,%2,%3};"
        : "+f"(c[0]), "+f"(c[1]), "+f"(c[2]), "+f"(c[3])
        : "r"(a[0]), "r"(a[1]), "r"(a[2]), "r"(a[3]), "r"(b0), "r"(b1));
}
__device__ __forceinline__ void cp16(uint32_t smem_addr, const void* gptr){
    asm volatile("cp.async.cg.shared.global [%0], [%1], 16;" :: "r"(smem_addr), "l"(gptr));
}
__device__ __forceinline__ void cp16z(uint32_t smem_addr, const void* gptr, uint32_t srcb){
    asm volatile("cp.async.cg.shared.global [%0], [%1], 16, %2;" :: "r"(smem_addr), "l"(gptr), "r"(srcb));
}
#define CP_COMMIT() asm volatile("cp.async.commit_group;" ::: "memory")
#define CP_WAIT1()  asm volatile("cp.async.wait_group 1;"  ::: "memory")

// ---------------- scratch ----------------
__device__ __align__(16) float g_QW [NRTOT*HSP];
__device__ __align__(16) float g_QhT[BATCH*HSP*LSEQ];
__device__ __align__(16) float g_Ah [NRTOT*HSP];
__device__ __align__(16) float g_Hm [NRTOT*HSP];
__device__ __align__(16) float g_Wcat[320*320];
__device__ __align__(16) float g_WgT [160*160];
__device__ __align__(16) float g_WtT [160*320];

// =====================================================================
// Kernel 0: weight prep
// =====================================================================
__global__ void __launch_bounds__(256) prep_kernel(
    const float* __restrict__ Wi, const float* __restrict__ Wu,
    const float* __restrict__ Wg, const float* __restrict__ Wt)
{
    int idx = blockIdx.x*256 + threadIdx.x;
    if (idx < 320*320){
        int n = idx / 320, k = idx - n*320;
        float v = 0.f;
        if (k < 300){
            if (n < 150)                  v = Wi[k*HH + n];
            else if (n >= 160 && n < 310) v = Wu[k*HH + (n-160)];
        }
        g_Wcat[idx] = rtf(v);
    }
    if (idx < 160*160){
        int n = idx / 160, k = idx - n*160;
        float v = (n < 150 && k < 150) ? Wg[k*HH + n] : 0.f;
        g_WgT[idx] = rtf(v);
    }
    if (idx < 160*320){
        int n = idx / 320, k = idx - n*320;
        float v = 0.f;
        if (n < 150){
            if (k < 150)                  v = Wt[k*HH + n];
            else if (k >= 160 && k < 310) v = Wt[(k - 160 + 150)*HH + n];
        }
        g_WtT[idx] = rtf(v);
    }
}

// =====================================================================
// Kernel 1 (MERGED): gate projections for Q and A in ONE launch.
//   blockIdx.x < 256: Q path (gate + smem-parked Qh + QhT store + fused QW GEMM)
//   blockIdx.x >= 256: A path (gate -> g_Ah)
// =====================================================================
#define GT_ABUF 2304
#define GT_BBUF 11520
#define GT_SMEM ((2*GT_ABUF + 2*GT_BBUF)*4)

__global__ void __launch_bounds__(256) gate_tc_kernel(
    const float* __restrict__ Q, const float* __restrict__ A,
    const float* __restrict__ bi, const float* __restrict__ bu,
    const float* __restrict__ bg)
{
    extern __shared__ __align__(16) float smem[];
    float* As = smem;
    float* Bs = smem + 2*GT_ABUF;

    const int tid = threadIdx.x, lane = tid & 31, wid = tid >> 5;
    const int wm = wid & 1, wn = wid >> 1;
    const int g = lane >> 2, t = lane & 3;
    const bool is_q = blockIdx.x < (NRTOT/64);
    const int row0 = (blockIdx.x & (NRTOT/64 - 1)) * 64;

    const float* __restrict__ X = is_q ? Q : A;
    const float* __restrict__ Ap = X + (size_t)row0*DIM;
    const uint32_t sA = smem_u32(As);
    const uint32_t sB = smem_u32(Bs);

    float acc[2][10][4];
    #pragma unroll
    for (int i = 0; i < 2; i++)
        #pragma unroll
        for (int n = 0; n < 10; n++)
            #pragma unroll
            for (int k = 0; k < 4; k++) acc[i][n][k] = 0.f;

    auto stage = [&](int c, int buf){
        const int kc = c*32;
        #pragma unroll
        for (int i = 0; i < 2; i++){
            int idx = tid + i*256;
            int r = idx >> 3, kq = idx & 7;
            int gk = kc + kq*4;
            uint32_t srcb = (gk + 4 <= DIM) ? 16u : 0u;
            const float* src = srcb ? (Ap + (size_t)r*DIM + gk) : Ap;
            cp16z(sA + (uint32_t)(buf*GT_ABUF + r*36 + kq*4)*4, src, srcb);
        }
        #pragma unroll
        for (int i = 0; i < 10; i++){
            int idx = tid + i*256;
            int r = idx >> 3, kq = idx & 7;
            cp16(sB + (uint32_t)(buf*GT_BBUF + r*36 + kq*4)*4,
                 g_Wcat + r*320 + kc + kq*4);
        }
    };

    stage(0, 0); CP_COMMIT();

    #pragma unroll 1
    for (int c = 0; c < 10; c++){
        if (c + 1 < 10) stage(c+1, (c+1)&1);
        CP_COMMIT();
        CP_WAIT1();
        __syncthreads();

        const float* Ab = As + (c&1)*GT_ABUF;
        const float* Bb = Bs + (c&1)*GT_BBUF;
        #pragma unroll
        for (int k0 = 0; k0 < 32; k0 += 8){
            uint32_t afr[2][4];
            #pragma unroll
            for (int mt = 0; mt < 2; mt++){
                const int m = wm*32 + mt*16;
                afr[mt][0] = rtfu(Ab[(m+g  )*36 + k0 + t    ]);
                afr[mt][1] = rtfu(Ab[(m+g+8)*36 + k0 + t    ]);
                afr[mt][2] = rtfu(Ab[(m+g  )*36 + k0 + t + 4]);
                afr[mt][3] = rtfu(Ab[(m+g+8)*36 + k0 + t + 4]);
            }
            #pragma unroll
            for (int nt = 0; nt < 10; nt++){
                const int n = (nt < 5) ? (wn*40 + nt*8) : (160 + wn*40 + (nt-5)*8);
                uint32_t b0 = __float_as_uint(Bb[(n+g)*36 + k0 + t    ]);
                uint32_t b1 = __float_as_uint(Bb[(n+g)*36 + k0 + t + 4]);
                mma1688(acc[0][nt], afr[0], b0, b1);
                mma1688(acc[1][nt], afr[1], b0, b1);
            }
        }
        __syncthreads();
    }
    __syncthreads();

    #pragma unroll
    for (int mt = 0; mt < 2; mt++){
        #pragma unroll
        for (int j2 = 0; j2 < 2; j2++){
            const int rl = wm*32 + mt*16 + g + j2*8;
            const int r  = row0 + rl;
            const int b = r >> 11, q = r & (LSEQ-1);
            #pragma unroll
            for (int ntp = 0; ntp < 5; ntp++){
                const int ncol = wn*40 + ntp*8 + 2*t;
                float h0 = 0.f, h1 = 0.f;
                if (ncol < HH){
                    float xi0 = acc[mt][ntp  ][2*j2    ] + __ldg(bi + ncol);
                    float xi1 = acc[mt][ntp  ][2*j2 + 1] + __ldg(bi + ncol + 1);
                    float xu0 = acc[mt][ntp+5][2*j2    ] + __ldg(bu + ncol);
                    float xu1 = acc[mt][ntp+5][2*j2 + 1] + __ldg(bu + ncol + 1);
                    h0 = rtf((1.f/(1.f + __expf(-xi0))) * tanhf(xu0));
                    h1 = rtf((1.f/(1.f + __expf(-xi1))) * tanhf(xu1));
                }
                if (is_q){
                    *(float2*)(Bs + rl*164 + ncol) = make_float2(h0, h1);
                    g_QhT[((size_t)b*HSP + ncol    )*LSEQ + q] = h0;
                    g_QhT[((size_t)b*HSP + ncol + 1)*LSEQ + q] = h1;
                } else {
                    *(float2*)(g_Ah + (size_t)r*HSP + ncol) = make_float2(h0, h1);
                }
            }
        }
    }

    if (is_q){
        const float* qhS = Bs;
        float* wgS = Bs + 10496;
        const uint32_t sWg = smem_u32(wgS);

        float acc2[2][5][4];
        #pragma unroll
        for (int i = 0; i < 2; i++)
            #pragma unroll
            for (int n = 0; n < 5; n++)
                #pragma unroll
                for (int k = 0; k < 4; k++) acc2[i][n][k] = 0.f;

        auto stageW = [&](int c, int buf){
            const int kc = c*32;
            #pragma unroll
            for (int i = 0; i < 5; i++){
                int idx = tid + i*256;
                int r = idx >> 3, kq = idx & 7;
                cp16(sWg + (uint32_t)(buf*5760 + r*36 + kq*4)*4,
                     g_WgT + r*160 + kc + kq*4);
            }
        };
        stageW(0, 0); CP_COMMIT();

        #pragma unroll 1
        for (int c = 0; c < 5; c++){
            if (c + 1 < 5) stageW(c+1, (c+1)&1);
            CP_COMMIT();
            CP_WAIT1();
            __syncthreads();

            const float* Wb = wgS + (c&1)*5760;
            #pragma unroll
            for (int k0 = 0; k0 < 32; k0 += 8){
                const int kk = c*32 + k0;
                uint32_t af[2][4];
                #pragma unroll
                for (int mt = 0; mt < 2; mt++){
                    const int m = wm*32 + mt*16;
                    af[mt][0] = __float_as_uint(qhS[(m+g  )*164 + kk + t    ]);
                    af[mt][1] = __float_as_uint(qhS[(m+g+8)*164 + kk + t    ]);
                    af[mt][2] = __float_as_uint(qhS[(m+g  )*164 + kk + t + 4]);
                    af[mt][3] = __float_as_uint(qhS[(m+g+8)*164 + kk + t + 4]);
                }
                #pragma unroll
                for (int nt = 0; nt < 5; nt++){
                    const int n = wn*40 + nt*8;
                    uint32_t b0 = __float_as_uint(Wb[(n+g)*36 + k0 + t    ]);
                    uint32_t b1 = __float_as_uint(Wb[(n+g)*36 + k0 + t + 4]);
                    mma1688(acc2[0][nt], af[0], b0, b1);
                    mma1688(acc2[1][nt], af[1], b0, b1);
                }
            }
            __syncthreads();
        }

        #pragma unroll
        for (int mt = 0; mt < 2; mt++){
            #pragma unroll
            for (int j2 = 0; j2 < 2; j2++){
                const int r = row0 + wm*32 + mt*16 + g + j2*8;
                #pragma unroll
                for (int nt = 0; nt < 5; nt++){
                    const int ncol = wn*40 + nt*8 + 2*t;
                    float v0 = 0.f, v1 = 0.f;
                    if (ncol < HH){
                        v0 = rtf(acc2[mt][nt][2*j2    ] + __ldg(bg + ncol));
                        v1 = rtf(acc2[mt][nt][2*j2 + 1] + __ldg(bg + ncol + 1));
                    }
                    *(float2*)(g_QW + (size_t)r*HSP + ncol) = make_float2(v0, v1);
                }
            }
        }
    }
}

// =====================================================================
// Kernel 2 (flash, R10 proven shape): 128 a-rows, 256 threads,
// q-chunks of 32, A-frags hoisted, no-max softmax.
// =====================================================================
#define FL_QW_OFF  20992
#define FL_QHT_OFF (20992 + 10496)
#define FL_SMEM    ((20992 + 10496 + 11520)*4)

__global__ void __launch_bounds__(256, 1) flash_kernel()
{
    extern __shared__ __align__(16) float smem[];
    float* sAh  = smem;                  // [128][164]
    float* sQW  = smem + FL_QW_OFF;      // [2][32][164]
    float* sQhT = smem + FL_QHT_OFF;     // [2][160][36]

    const int tid = threadIdx.x, lane = tid & 31, w = tid >> 5;
    const int g = lane >> 2, t = lane & 3;
    const int b = blockIdx.y, a0 = blockIdx.x*128;
    const int m0 = w*16;

    const uint32_t sbAh  = smem_u32(sAh);
    const uint32_t sbQW  = smem_u32(sQW);
    const uint32_t sbQhT = smem_u32(sQhT);

    const float* __restrict__ AhP  = g_Ah  + ((size_t)b*LSEQ + a0)*HSP;
    const float* __restrict__ QWP  = g_QW  + (size_t)b*LSEQ*HSP;
    const float* __restrict__ QhTP = g_QhT + (size_t)b*HSP*LSEQ;

    #pragma unroll
    for (int i = 0; i < 20; i++){
        int idx = tid + i*256;
        int r = idx / 40, kq = idx - r*40;
        cp16(sbAh + (uint32_t)(r*164 + kq*4)*4, AhP + (size_t)r*HSP + kq*4);
    }
    auto stageQ = [&](int c, int buf){
        const int qc = c*32;
        #pragma unroll
        for (int i = 0; i < 5; i++){
            int idx = tid + i*256;
            int r = idx / 40, kq = idx - r*40;
            cp16(sbQW + (uint32_t)(buf*(32*164) + r*164 + kq*4)*4,
                 QWP + (size_t)(qc + r)*HSP + kq*4);
        }
        #pragma unroll
        for (int i = 0; i < 5; i++){
            int idx = tid + i*256;
            int r = idx >> 3, qq = idx & 7;
            cp16(sbQhT + (uint32_t)(buf*(160*36) + r*36 + qq*4)*4,
                 QhTP + (size_t)r*LSEQ + qc + qq*4);
        }
    };
    stageQ(0, 0); CP_COMMIT();
    stageQ(1, 1); CP_COMMIT();

    CP_WAIT1();
    __syncthreads();
    uint32_t afr[20][4];
    #pragma unroll
    for (int ks = 0; ks < 20; ks++){
        const int k0 = ks*8;
        afr[ks][0] = __float_as_uint(sAh[(m0+g  )*164 + k0 + t    ]);
        afr[ks][1] = __float_as_uint(sAh[(m0+g+8)*164 + k0 + t    ]);
        afr[ks][2] = __float_as_uint(sAh[(m0+g  )*164 + k0 + t + 4]);
        afr[ks][3] = __float_as_uint(sAh[(m0+g+8)*164 + k0 + t + 4]);
    }

    float hm[20][4];
    #pragma unroll
    for (int n2 = 0; n2 < 20; n2++)
        #pragma unroll
        for (int k = 0; k < 4; k++) hm[n2][k] = 0.f;
    float lr0 = 0.f, lr1 = 0.f;

    #pragma unroll 1
    for (int c = 0; c < 64; c++){
        const int p = c & 1;
        CP_WAIT1();
        __syncthreads();

        const float* QWb  = sQW  + p*(32*164);
        const float* QhTb = sQhT + p*(160*36);

        // ---- GEMM1: S chunk [16 rows x 32 q], K=160 ----
        float sc[4][4];
        #pragma unroll
        for (int nt = 0; nt < 4; nt++)
            #pragma unroll
            for (int k = 0; k < 4; k++) sc[nt][k] = 0.f;

        #pragma unroll
        for (int ks = 0; ks < 20; ks++){
            const int k0 = ks*8;
            #pragma unroll
            for (int nt = 0; nt < 4; nt++){
                uint32_t b0 = __float_as_uint(QWb[(nt*8+g)*164 + k0 + t    ]);
                uint32_t b1 = __float_as_uint(QWb[(nt*8+g)*164 + k0 + t + 4]);
                mma1688(sc[nt], afr[ks], b0, b1);
            }
        }

        // ---- softmax numerator (no max shift) + row sums ----
        float pv[4][4];
        float rs0 = 0.f, rs1 = 0.f;
        #pragma unroll
        for (int nt = 0; nt < 4; nt++){
            pv[nt][0] = __expf(sc[nt][0]);
            pv[nt][1] = __expf(sc[nt][1]);
            pv[nt][2] = __expf(sc[nt][2]);
            pv[nt][3] = __expf(sc[nt][3]);
            rs0 += pv[nt][0] + pv[nt][1];
            rs1 += pv[nt][2] + pv[nt][3];
        }
        rs0 += __shfl_xor_sync(0xffffffffu, rs0, 1);
        rs0 += __shfl_xor_sync(0xffffffffu, rs0, 2);
        rs1 += __shfl_xor_sync(0xffffffffu, rs1, 1);
        rs1 += __shfl_xor_sync(0xffffffffu, rs1, 2);
        lr0 += rs0; lr1 += rs1;

        // ---- P: C-frag -> A-frag via quad shfl ----
        uint32_t pa[4][4];
        const int qs  = (lane & ~3) | (t >> 1);
        const int qs2 = qs | 2;
        const bool odd = (t & 1);
        #pragma unroll
        for (int nt = 0; nt < 4; nt++){
            float x0 = __shfl_sync(0xffffffffu, pv[nt][0], qs);
            float x1 = __shfl_sync(0xffffffffu, pv[nt][1], qs);
            float x2 = __shfl_sync(0xffffffffu, pv[nt][2], qs);
            float x3 = __shfl_sync(0xffffffffu, pv[nt][3], qs);
            float y0 = __shfl_sync(0xffffffffu, pv[nt][0], qs2);
            float y1 = __shfl_sync(0xffffffffu, pv[nt][1], qs2);
            float y2 = __shfl_sync(0xffffffffu, pv[nt][2], qs2);
            float y3 = __shfl_sync(0xffffffffu, pv[nt][3], qs2);
            pa[nt][0] = rtfu(odd ? x1 : x0);
            pa[nt][1] = rtfu(odd ? x3 : x2);
            pa[nt][2] = rtfu(odd ? y1 : y0);
            pa[nt][3] = rtfu(odd ? y3 : y2);
        }

        // ---- GEMM2: Hm[16 x 160] += P[16 x 32] @ QhT^T ----
        #pragma unroll
        for (int nt = 0; nt < 4; nt++){
            const int k0 = nt*8;
            #pragma unroll
            for (int n2 = 0; n2 < 20; n2++){
                uint32_t b0 = __float_as_uint(QhTb[(n2*8+g)*36 + k0 + t    ]);
                uint32_t b1 = __float_as_uint(QhTb[(n2*8+g)*36 + k0 + t + 4]);
                mma1688(hm[n2], pa[nt], b0, b1);
            }
        }

        __syncthreads();
        if (c + 2 < 64) stageQ(c+2, p);
        CP_COMMIT();
    }

    const float inv0 = 1.f / lr0, inv1 = 1.f / lr1;
    float* __restrict__ H0 = g_Hm + ((size_t)b*LSEQ + a0 + m0 + g    )*HSP;
    float* __restrict__ H1 = g_Hm + ((size_t)b*LSEQ + a0 + m0 + g + 8)*HSP;
    #pragma unroll
    for (int n2 = 0; n2 < 20; n2++){
        const int col = n2*8 + 2*t;
        *(float2*)(H0 + col) = make_float2(hm[n2][0]*inv0, hm[n2][1]*inv0);
        *(float2*)(H1 + col) = make_float2(hm[n2][2]*inv1, hm[n2][3]*inv1);
    }
}

// =====================================================================
// Kernel 5: T = relu([Ah | Hm] @ WtT + bt) (mma tf32)
// =====================================================================
#define OT_ABUF 2304
#define OT_BBUF 5760
#define OT_SMEM ((2*OT_ABUF + 2*OT_BBUF)*4)

__global__ void __launch_bounds__(256) out_tc_kernel(
    const float* __restrict__ bt, float* __restrict__ out)
{
    extern __shared__ __align__(16) float smem[];
    float* As = smem;
    float* Bs = smem + 2*OT_ABUF;

    const int tid = threadIdx.x, lane = tid & 31, wid = tid >> 5;
    const int wm = wid & 1, wn = wid >> 1;
    const int g = lane >> 2, t = lane & 3;
    const int row0 = blockIdx.x * 64;

    const uint32_t sA = smem_u32(As);
    const uint32_t sB = smem_u32(Bs);

    float acc[2][5][4];
    #pragma unroll
    for (int i = 0; i < 2; i++)
        #pragma unroll
        for (int n = 0; n < 5; n++)
            #pragma unroll
            for (int k = 0; k < 4; k++) acc[i][n][k] = 0.f;

    auto stage = [&](int c, int buf){
        const int kc = c*32;
        const float* __restrict__ Sp = (c < 5)
            ? (g_Ah + (size_t)row0*HSP + kc)
            : (g_Hm + (size_t)row0*HSP + (kc - 160));
        #pragma unroll
        for (int i = 0; i < 2; i++){
            int idx = tid + i*256;
            int r = idx >> 3, kq = idx & 7;
            cp16(sA + (uint32_t)(buf*OT_ABUF + r*36 + kq*4)*4,
                 Sp + (size_t)r*HSP + kq*4);
        }
        #pragma unroll
        for (int i = 0; i < 5; i++){
            int idx = tid + i*256;
            int r = idx >> 3, kq = idx & 7;
            cp16(sB + (uint32_t)(buf*OT_BBUF + r*36 + kq*4)*4,
                 g_WtT + r*320 + kc + kq*4);
        }
    };

    stage(0, 0); CP_COMMIT();

    #pragma unroll 1
    for (int c = 0; c < 10; c++){
        if (c + 1 < 10) stage(c+1, (c+1)&1);
        CP_COMMIT();
        CP_WAIT1();
        __syncthreads();

        const float* Ab = As + (c&1)*OT_ABUF;
        const float* Bb = Bs + (c&1)*OT_BBUF;
        #pragma unroll
        for (int k0 = 0; k0 < 32; k0 += 8){
            uint32_t afr[2][4];
            #pragma unroll
            for (int mt = 0; mt < 2; mt++){
                const int m = wm*32 + mt*16;
                afr[mt][0] = rtfu(Ab[(m+g  )*36 + k0 + t    ]);
                afr[mt][1] = rtfu(Ab[(m+g+8)*36 + k0 + t    ]);
                afr[mt][2] = rtfu(Ab[(m+g  )*36 + k0 + t + 4]);
                afr[mt][3] = rtfu(Ab[(m+g+8)*36 + k0 + t + 4]);
            }
            #pragma unroll
            for (int nt = 0; nt < 5; nt++){
                const int n = wn*40 + nt*8;
                uint32_t b0 = __float_as_uint(Bb[(n+g)*36 + k0 + t    ]);
                uint32_t b1 = __float_as_uint(Bb[(n+g)*36 + k0 + t + 4]);
                mma1688(acc[0][nt], afr[0], b0, b1);
                mma1688(acc[1][nt], afr[1], b0, b1);
            }
        }
        __syncthreads();
    }

    #pragma unroll
    for (int mt = 0; mt < 2; mt++){
        #pragma unroll
        for (int j2 = 0; j2 < 2; j2++){
            const int r = row0 + wm*32 + mt*16 + g + j2*8;
            #pragma unroll
            for (int nt = 0; nt < 5; nt++){
                const int ncol = wn*40 + nt*8 + 2*t;
                if (ncol < HH){
                    float v0 = fmaxf(acc[mt][nt][2*j2    ] + __ldg(bt + ncol),     0.f);
                    float v1 = fmaxf(acc[mt][nt][2*j2 + 1] + __ldg(bt + ncol + 1), 0.f);
                    *(float2*)(out + (size_t)r*HH + ncol) = make_float2(v0, v1);
                }
            }
        }
    }
}

// =====================================================================
extern "C" void kernel_launch(void* const* d_in, const int* in_sizes, int n_in,
                              void* d_out, int out_size)
{
    (void)in_sizes; (void)n_in; (void)out_size;
    const float* Q  = (const float*)d_in[0];
    const float* A  = (const float*)d_in[1];
    const float* Wi = (const float*)d_in[2];
    const float* Wu = (const float*)d_in[3];
    const float* Wg = (const float*)d_in[4];
    const float* Wt = (const float*)d_in[5];
    const float* bi = (const float*)d_in[6];
    const float* bu = (const float*)d_in[7];
    const float* bg = (const float*)d_in[8];
    const float* bt = (const float*)d_in[9];
    float* out = (float*)d_out;

    static bool attr_done = false;
    if (!attr_done){
        cudaFuncSetAttribute(gate_tc_kernel, cudaFuncAttributeMaxDynamicSharedMemorySize, GT_SMEM);
        cudaFuncSetAttribute(flash_kernel,   cudaFuncAttributeMaxDynamicSharedMemorySize, FL_SMEM);
        cudaFuncSetAttribute(out_tc_kernel,  cudaFuncAttributeMaxDynamicSharedMemorySize, OT_SMEM);
        attr_done = true;
    }

    prep_kernel<<<400, 256>>>(Wi, Wu, Wg, Wt);
    gate_tc_kernel<<<2*(NRTOT/64), 256, GT_SMEM>>>(Q, A, bi, bu, bg);
    flash_kernel<<<dim3(LSEQ/128, BATCH), 256, FL_SMEM>>>();
    out_tc_kernel<<<NRTOT/64, 256, OT_SMEM>>>(bt, out);
}